// round 2
// baseline (speedup 1.0000x reference)
#include <cuda_runtime.h>
#include <math.h>

// Phase 1: energies[b*2048 + s] = dot(hidden[b,:], enc[s,b,:])
// One warp handles ROWS_PER_WARP=8 rows sharing the same b (consecutive s),
// so hidden[b] is loaded into registers ONCE per warp (8x less hidden traffic).
// enc is streamed with __ldcs (evict-first) to keep hidden resident in L1/L2.
#define ROWS_PER_WARP 8

__global__ void __launch_bounds__(256) dot_kernel(
    const float* __restrict__ hidden,   // [64, 1024]
    const float* __restrict__ enc,      // [2048, 64, 1024]
    float* __restrict__ energies)       // [64, 2048]
{
    int gwarp = (blockIdx.x * blockDim.x + threadIdx.x) >> 5;   // 0..16383
    int lane  = threadIdx.x & 31;

    int b     = gwarp & 63;
    int sbase = (gwarp >> 6) * ROWS_PER_WARP;

    // hidden[b] -> registers, once per warp (8 float4 = 32 regs)
    const float4* h = reinterpret_cast<const float4*>(hidden + (size_t)b * 1024);
    float4 hv[8];
#pragma unroll
    for (int i = 0; i < 8; i++)
        hv[i] = __ldg(&h[lane + i * 32]);

    float acc[ROWS_PER_WARP];
#pragma unroll
    for (int j = 0; j < ROWS_PER_WARP; j++) {
        const float4* row = reinterpret_cast<const float4*>(
            enc + ((size_t)(sbase + j) * 64 + b) * 1024);
        float a = 0.0f;
#pragma unroll
        for (int i = 0; i < 8; i++) {
            float4 e = __ldcs(&row[lane + i * 32]);   // evict-first stream
            a = fmaf(e.x, hv[i].x, a);
            a = fmaf(e.y, hv[i].y, a);
            a = fmaf(e.z, hv[i].z, a);
            a = fmaf(e.w, hv[i].w, a);
        }
        acc[j] = a;
    }

    // xor-reduce each row sum to all lanes; lane j stores row j (coalesced 32B)
#pragma unroll
    for (int j = 0; j < ROWS_PER_WARP; j++) {
#pragma unroll
        for (int o = 16; o; o >>= 1)
            acc[j] += __shfl_xor_sync(0xffffffffu, acc[j], o);
    }
    if (lane < ROWS_PER_WARP)
        energies[b * 2048 + sbase + lane] = acc[lane];
}

// Phase 2: in-place softmax over S=2048 per batch row. 64 blocks x 1024 threads.
__global__ void __launch_bounds__(1024) softmax_kernel(float* __restrict__ out)
{
    __shared__ float red[32];

    int b   = blockIdx.x;
    int tid = threadIdx.x;
    int lane = tid & 31;
    int wid  = tid >> 5;
    float* p = out + (size_t)b * 2048;

    float v0 = p[tid];
    float v1 = p[tid + 1024];

    // --- max reduce ---
    float m = fmaxf(v0, v1);
#pragma unroll
    for (int o = 16; o; o >>= 1)
        m = fmaxf(m, __shfl_xor_sync(0xffffffffu, m, o));
    if (lane == 0) red[wid] = m;
    __syncthreads();
    if (tid < 32) {
        float x = red[tid];
#pragma unroll
        for (int o = 16; o; o >>= 1)
            x = fmaxf(x, __shfl_xor_sync(0xffffffffu, x, o));
        if (tid == 0) red[0] = x;
    }
    __syncthreads();
    m = red[0];
    __syncthreads();

    // --- exp + sum reduce ---
    v0 = __expf(v0 - m);
    v1 = __expf(v1 - m);
    float s = v0 + v1;
#pragma unroll
    for (int o = 16; o; o >>= 1)
        s += __shfl_xor_sync(0xffffffffu, s, o);
    if (lane == 0) red[wid] = s;
    __syncthreads();
    if (tid < 32) {
        float x = red[tid];
#pragma unroll
        for (int o = 16; o; o >>= 1)
            x += __shfl_xor_sync(0xffffffffu, x, o);
        if (tid == 0) red[0] = x;
    }
    __syncthreads();
    float inv = 1.0f / red[0];

    p[tid]        = v0 * inv;
    p[tid + 1024] = v1 * inv;
}

extern "C" void kernel_launch(void* const* d_in, const int* in_sizes, int n_in,
                              void* d_out, int out_size)
{
    const float* hidden = (const float*)d_in[0];   // [1, 64, 1024]
    const float* enc    = (const float*)d_in[1];   // [2048, 64, 1024]
    float* out          = (float*)d_out;           // [64, 1, 2048]

    // 16384 warps (8 rows each) -> 2048 blocks of 256 threads
    dot_kernel<<<2048, 256>>>(hidden, enc, out);
    softmax_kernel<<<64, 1024>>>(out);
}